// round 5
// baseline (speedup 1.0000x reference)
#include <cuda_runtime.h>
#include <cuda_bf16.h>
#include <cstdint>

#define NCARDS 50000
#define NJ 49999
#define B 1024
#define JC 38                // j-chunks (grid.x)
#define CHUNK 1344           // cols per chunk (21 tiles of 64)
#define NJ_PAD (JC*CHUNK)    // 51072
#define TILES 21
#define NCTA 304             // 38*8
#define LOG2E 1.4426950408889634f
#define KL_EPS 1e-7f
#define LG2_EPS -23.253496664211536f

// smem layout for k_gemm4 (bytes): [E0 9216][E1 9216][adj0 33792][adj1 33792]
#define ES_STRIDE 144
#define ES_BYTES  (64*ES_STRIDE)      // 9216
#define ADJ_PITCH 66
#define ADJ_BYTES (128*ADJ_PITCH*4)   // 33792
#define SMEM_G4 (2*ES_BYTES + 2*ADJ_BYTES)  // 86016

// ---------------- device scratch ----------------
__device__ __nv_bfloat16 g_eB[(size_t)NJ_PAD*64];
__device__ __nv_bfloat16 g_aBF[B*64];
__device__ float g_acc[B*4];     // per-row {Z, T1, T2, T3}
__device__ float g_cross[B], g_lse2[B];
__device__ int   g_flag[B];
__device__ unsigned g_ctr;

// ---------------- helpers ----------------
__device__ __forceinline__ float ex2f_(float x){ float r; asm("ex2.approx.f32 %0, %1;" : "=f"(r) : "f"(x)); return r; }
__device__ __forceinline__ float lg2f_(float x){ float r; asm("lg2.approx.f32 %0, %1;" : "=f"(r) : "f"(x)); return r; }
__device__ __forceinline__ uint32_t smem_u32(const void* p){
    uint32_t a; asm("{ .reg .u64 t; cvta.to.shared.u64 t, %1; cvt.u32.u64 %0, t; }" : "=r"(a) : "l"(p)); return a; }

__device__ __forceinline__ void mma16816(float* c, const uint32_t* a, uint32_t b0, uint32_t b1){
    asm volatile("mma.sync.aligned.m16n8k16.row.col.f32.bf16.bf16.f32 "
        "{%0,%1,%2,%3}, {%4,%5,%6,%7}, {%8,%9}, {%0,%1,%2,%3};"
        : "+f"(c[0]), "+f"(c[1]), "+f"(c[2]), "+f"(c[3])
        : "r"(a[0]), "r"(a[1]), "r"(a[2]), "r"(a[3]), "r"(b0), "r"(b1));
}

__device__ __forceinline__ void upd(float L, float y, float& z, float& t1, float& t2, float& t3){
    y = fmaxf(y, KL_EPS);                 // upper clip never binds (y<1 by construction)
    z += ex2f_(L);
    t1 = fmaf(y, L, t1);
    t2 += y;
    t3 = fmaf(y, lg2f_(y), t3);
}

// ---------------- kernel: normalize E[1:], bf16 [j][k], zero-pad ----------------
__global__ void k_enorm(const float* __restrict__ emb){
    int wid = threadIdx.x>>5, lane = threadIdx.x&31;
    int j = blockIdx.x*8 + wid;
    float2 v = make_float2(0.f, 0.f);
    if (j < NJ) v = ((const float2*)emb)[(size_t)(j+1)*32 + lane];
    float s = v.x*v.x + v.y*v.y;
#pragma unroll
    for(int o=16;o;o>>=1) s += __shfl_xor_sync(0xffffffffu, s, o);
    float inv = rsqrtf(fmaxf(s, 1e-12f));
    __nv_bfloat162 o2;
    o2.x = __float2bfloat16_rn(v.x*inv);
    o2.y = __float2bfloat16_rn(v.y*inv);
    ((__nv_bfloat162*)g_eB)[(size_t)j*32 + lane] = o2;
}

// ---------------- kernel: gather + MLP + l2norm, fold t*log2e, bf16 ----------------
__global__ void __launch_bounds__(256) k_mlp(const int* __restrict__ cards, const float* __restrict__ emb,
        const float* __restrict__ W1, const float* __restrict__ b1,
        const float* __restrict__ W2, const float* __restrict__ b2,
        const float* __restrict__ temp){
    extern __shared__ float dyn[];
    float* sW1 = dyn;              // 16384
    float* sW2 = dyn + 16384;      // 16384
    float* se  = dyn + 32768;      // 1024
    float* sh  = dyn + 33792;      // 4096
    float* so  = dyn + 37888;      // 1024
    float* ssc = dyn + 38912;      // 16
    int t = threadIdx.x;
    int b0 = blockIdx.x*16;
    const float4* W1v = (const float4*)W1; float4* s1v = (float4*)sW1;
    const float4* W2v = (const float4*)W2; float4* s2v = (float4*)sW2;
#pragma unroll
    for(int i=0;i<16;i++) s1v[t + i*256] = W1v[t + i*256];
#pragma unroll
    for(int i=0;i<16;i++) s2v[t + i*256] = W2v[t + i*256];
#pragma unroll
    for(int i=0;i<4;i++){ int idx = t + i*256; int bi = idx>>6, k = idx&63;
        se[idx] = emb[(size_t)cards[b0+bi]*64 + k]; }
    __syncthreads();
    float bb1 = b1[t];
    for(int bi=0;bi<16;bi++){
        float h = bb1;
#pragma unroll
        for(int k=0;k<64;k++) h = fmaf(se[bi*64+k], sW1[k*256+t], h);
        sh[bi*256+t] = fmaxf(h, 0.f);
    }
    __syncthreads();
    int d = t&63, g = t>>6;
    float bb2 = b2[d];
    for(int r=0;r<4;r++){
        int bi = g*4 + r;
        float o = bb2;
#pragma unroll 8
        for(int j=0;j<256;j++) o = fmaf(sh[bi*256+j], sW2[j*64+d], o);
        so[bi*64+d] = o;
    }
    __syncthreads();
    if (t < 16){
        float s = 0.f;
#pragma unroll
        for(int dd=0;dd<64;dd++){ float v = so[t*64+dd]; s = fmaf(v, v, s); }
        ssc[t] = temp[0]*LOG2E*rsqrtf(fmaxf(s, 1e-12f));
    }
    __syncthreads();
#pragma unroll
    for(int i=0;i<4;i++){ int idx = t + i*256; int bi = idx>>6;
        g_aBF[(size_t)b0*64 + idx] = __float2bfloat16_rn(so[idx]*ssc[bi]); }
}

// ---------------- kernel: init accumulators/counter/flags ----------------
__global__ void k_init(){
    int i = blockIdx.x*256 + threadIdx.x;   // grid 16 x 256 = 4096
    g_acc[i] = 0.f;
    if (i < B) g_flag[i] = 0;
    if (i == 0) g_ctr = 0u;
}

// ---------------- staging ----------------
__device__ __forceinline__ void stage_tile(int buf, int j0, int jv, const float* __restrict__ adj,
                                           int rt, uint32_t smbase, int tid){
    uint32_t eb = smbase + buf*ES_BYTES;
    uint32_t ab = smbase + 2*ES_BYTES + buf*ADJ_BYTES;
#pragma unroll
    for(int i=0;i<2;i++){
        int c = tid + i*256;                 // 512 chunks of 16B
        int row = c>>3, seg = c&7;
        uint32_t dst = eb + row*ES_STRIDE + seg*16;
        const char* src = (const char*)g_eB + (size_t)(j0+row)*128 + seg*16;
        asm volatile("cp.async.cg.shared.global [%0], [%1], 16;" :: "r"(dst), "l"(src));
    }
    if (jv == 64){
#pragma unroll
        for(int i=0;i<32;i++){
            int idx = tid + i*256;
            int row = idx>>6, col = idx&63;
            uint32_t dst = ab + (uint32_t)(row*ADJ_PITCH + col)*4u;
            const float* src = adj + (size_t)(rt*128+row)*NJ + j0 + col;
            asm volatile("cp.async.ca.shared.global [%0], [%1], 4;" :: "r"(dst), "l"(src));
        }
    } else {
        for(int i=0;i<32;i++){
            int idx = tid + i*256;
            int row = idx>>6, col = idx&63;
            float v = 0.f;
            if (col < jv) v = __ldcs(adj + (size_t)(rt*128+row)*NJ + j0 + col);
            uint32_t dst = ab + (uint32_t)(row*ADJ_PITCH + col)*4u;
            asm volatile("st.shared.f32 [%0], %1;" :: "r"(dst), "f"(v));
        }
    }
    asm volatile("cp.async.commit_group;" ::: "memory");
}

// ---------------- kernel: HMMA GEMM + fused stats + last-CTA finalize ----------------
// grid (38, 8), 256 threads. M-tile 128, N-tile 64.
__global__ void __launch_bounds__(256) k_gemm4(const float* __restrict__ adj,
                                               const float* __restrict__ temp,
                                               float* __restrict__ out){
    extern __shared__ __align__(16) char sm4[];
    const uint32_t smbase = smem_u32(sm4);
    int tid = threadIdx.x;
    int wid = tid>>5, lane = tid&31, g = lane>>2, tg = lane&3;
    int jc = blockIdx.x, rt = blockIdx.y;
    int jstart = jc*CHUNK;
    int nvalid = NJ - jstart;
    int ntiles = (nvalid + 63)>>6; if (ntiles > TILES) ntiles = TILES;

    // A fragments: rows rt*128 + wid*16 + g (+8), all 4 k-tiles
    uint32_t A[4][4];
    {
        int r0 = rt*128 + wid*16 + g;
        const uint32_t* a0 = (const uint32_t*)(g_aBF + (size_t)r0*64);
        const uint32_t* a1 = (const uint32_t*)(g_aBF + (size_t)(r0+8)*64);
#pragma unroll
        for(int kt=0;kt<4;kt++){
            A[kt][0]=a0[kt*8+tg];   A[kt][1]=a1[kt*8+tg];
            A[kt][2]=a0[kt*8+tg+4]; A[kt][3]=a1[kt*8+tg+4];
        }
    }

    float Z[2]={0.f,0.f}, T1[2]={0.f,0.f}, T2[2]={0.f,0.f}, T3[2]={0.f,0.f};

    {
        int jv0 = nvalid; if (jv0 > 64) jv0 = 64;
        stage_tile(0, jstart, jv0, adj, rt, smbase, tid);
    }

    for(int t=0;t<ntiles;t++){
        int j0 = jstart + (t<<6);
        int jv = NJ - j0; if (jv > 64) jv = 64;
        bool hasNext = (t+1) < ntiles;
        if (hasNext){
            int j1 = j0 + 64;
            int jv1 = NJ - j1; if (jv1 > 64) jv1 = 64;
            stage_tile((t+1)&1, j1, jv1, adj, rt, smbase, tid);
            asm volatile("cp.async.wait_group 1;" ::: "memory");
        } else {
            asm volatile("cp.async.wait_group 0;" ::: "memory");
        }
        __syncthreads();

        const char*  Es    = sm4 + (t&1)*ES_BYTES;
        const float* sadjB = (const float*)(sm4 + 2*ES_BYTES + (t&1)*ADJ_BYTES);

        float acc[8][4];
#pragma unroll
        for(int nt=0;nt<8;nt++){ acc[nt][0]=0.f; acc[nt][1]=0.f; acc[nt][2]=0.f; acc[nt][3]=0.f; }

#pragma unroll
        for(int kt=0;kt<4;kt++){
#pragma unroll
            for(int nt=0;nt<8;nt++){
                const char* bp = Es + (nt*8+g)*ES_STRIDE + kt*32 + tg*4;
                uint32_t b0 = *(const uint32_t*)bp;
                uint32_t b1 = *(const uint32_t*)(bp + 16);
                mma16816(acc[nt], A[kt], b0, b1);
            }
        }

        int r0l = wid*16 + g;
        if (jv == 64){
#pragma unroll
            for(int nt=0;nt<8;nt++){
                int c0 = nt*8 + tg*2;
                float2 ya = *(const float2*)(sadjB + r0l*ADJ_PITCH + c0);
                float2 yb = *(const float2*)(sadjB + (r0l+8)*ADJ_PITCH + c0);
                upd(acc[nt][0], ya.x, Z[0],T1[0],T2[0],T3[0]);
                upd(acc[nt][1], ya.y, Z[0],T1[0],T2[0],T3[0]);
                upd(acc[nt][2], yb.x, Z[1],T1[1],T2[1],T3[1]);
                upd(acc[nt][3], yb.y, Z[1],T1[1],T2[1],T3[1]);
            }
        } else {
#pragma unroll
            for(int nt=0;nt<8;nt++){
                int c0 = nt*8 + tg*2;
                if (c0 < jv){
                    float2 ya = *(const float2*)(sadjB + r0l*ADJ_PITCH + c0);
                    float2 yb = *(const float2*)(sadjB + (r0l+8)*ADJ_PITCH + c0);
                    upd(acc[nt][0], ya.x, Z[0],T1[0],T2[0],T3[0]);
                    upd(acc[nt][2], yb.x, Z[1],T1[1],T2[1],T3[1]);
                    if (c0 + 1 < jv){
                        upd(acc[nt][1], ya.y, Z[0],T1[0],T2[0],T3[0]);
                        upd(acc[nt][3], yb.y, Z[1],T1[1],T2[1],T3[1]);
                    }
                }
            }
        }
        __syncthreads();
    }

    // reduce over tg lanes, then atomic merge
#pragma unroll
    for(int r=0;r<2;r++){
#pragma unroll
        for(int off=1; off<4; off<<=1){
            Z[r]  += __shfl_xor_sync(0xffffffffu, Z[r],  off);
            T1[r] += __shfl_xor_sync(0xffffffffu, T1[r], off);
            T2[r] += __shfl_xor_sync(0xffffffffu, T2[r], off);
            T3[r] += __shfl_xor_sync(0xffffffffu, T3[r], off);
        }
    }
    if (tg == 0){
#pragma unroll
        for(int r=0;r<2;r++){
            int row = rt*128 + wid*16 + g + r*8;
            atomicAdd(&g_acc[row*4+0], Z[r]);
            atomicAdd(&g_acc[row*4+1], T1[r]);
            atomicAdd(&g_acc[row*4+2], T2[r]);
            atomicAdd(&g_acc[row*4+3], T3[r]);
        }
    }

    // last CTA finalizes
    __threadfence();
    __shared__ unsigned s_last;
    if (tid == 0) s_last = (atomicAdd(&g_ctr, 1u) == NCTA-1) ? 1u : 0u;
    __syncthreads();
    if (!s_last) return;

    float* red = (float*)sm4;
    float T = temp[0];
    float thresh = -LG2_EPS - T*LOG2E - 0.25f;   // conservative: L >= -t*log2e
    float local = 0.f;
#pragma unroll
    for(int i=0;i<4;i++){
        int b = tid + i*256;
        float Zb, T1b, T2b, T3b;
        asm("ld.global.cg.f32 %0, [%1];" : "=f"(Zb)  : "l"(&g_acc[b*4+0]));
        asm("ld.global.cg.f32 %0, [%1];" : "=f"(T1b) : "l"(&g_acc[b*4+1]));
        asm("ld.global.cg.f32 %0, [%1];" : "=f"(T2b) : "l"(&g_acc[b*4+2]));
        asm("ld.global.cg.f32 %0, [%1];" : "=f"(T3b) : "l"(&g_acc[b*4+3]));
        float lse2 = lg2f_(Zb);
        float cross = T1b - lse2*T2b;
        g_lse2[b] = lse2;
        g_cross[b] = cross;
        if (lse2 > thresh) g_flag[b] = 1;
        local += T3b - cross;
    }
    red[tid] = local;
    __syncthreads();
    for(int s=128;s;s>>=1){ if (tid < s) red[tid] += red[tid+s]; __syncthreads(); }
    if (tid == 0) out[0] = red[0]*(1.0f/(float)B) + T*T*0.01f;
}

// ---------------- kernel: exact clipped fixup (cold) ----------------
__global__ void k_fixup(const float* __restrict__ adj, float* __restrict__ out){
    __shared__ int flags[128];
    __shared__ int any;
    __shared__ float a[64];
    __shared__ float red[256];
    int b0 = blockIdx.x*128;
    int t = threadIdx.x;
    if (t == 0) any = 0;
    __syncthreads();
    if (t < 128){ int f = g_flag[b0+t]; flags[t] = f; if (f) any = 1; }
    __syncthreads();
    if (!any) return;
    for(int r=0;r<128;r++){
        if (!flags[r]) continue;
        int b = b0 + r;
        if (t < 64) a[t] = __bfloat162float(g_aBF[b*64 + t]);
        __syncthreads();
        float lse2 = g_lse2[b];
        float cr = 0.f;
        for(int j=t; j<NJ; j+=256){
            float L = 0.f;
#pragma unroll
            for(int k=0;k<64;k++) L = fmaf(a[k], __bfloat162float(g_eB[(size_t)j*64 + k]), L);
            float y = fmaxf(adj[(size_t)b*NJ + j], KL_EPS);
            cr = fmaf(y, fmaxf(L - lse2, LG2_EPS), cr);
        }
        red[t] = cr; __syncthreads();
        for(int s=128;s;s>>=1){ if (t < s) red[t] += red[t+s]; __syncthreads(); }
        if (t == 0) atomicAdd(out, (g_cross[b] - red[0])*(1.0f/(float)B));
        __syncthreads();
    }
}

// ---------------- launch ----------------
extern "C" void kernel_launch(void* const* d_in, const int* in_sizes, int n_in,
                              void* d_out, int out_size){
    const int*   cards = (const int*)  d_in[0];
    const float* adj   = (const float*)d_in[1];
    const float* emb   = (const float*)d_in[2];
    const float* W1    = (const float*)d_in[3];
    const float* b1    = (const float*)d_in[4];
    const float* W2    = (const float*)d_in[5];
    const float* b2    = (const float*)d_in[6];
    const float* temp  = (const float*)d_in[7];

    cudaFuncSetAttribute(k_mlp,   cudaFuncAttributeMaxDynamicSharedMemorySize, 155712);
    cudaFuncSetAttribute(k_gemm4, cudaFuncAttributeMaxDynamicSharedMemorySize, SMEM_G4);

    k_enorm<<<NJ_PAD/8, 256>>>(emb);                          // idx 0
    k_mlp<<<64, 256, 155712>>>(cards, emb, W1, b1, W2, b2, temp); // idx 1
    k_init<<<16, 256>>>();                                    // idx 2
    k_gemm4<<<dim3(JC, 8), 256, SMEM_G4>>>(adj, temp, (float*)d_out); // idx 3 (ncu target)
    k_fixup<<<8, 256>>>(adj, (float*)d_out);                  // idx 4
}

// round 8
// speedup vs baseline: 1862.1507x; 1862.1507x over previous
#include <cuda_runtime.h>
#include <cuda_bf16.h>
#include <cstdint>

#define NCARDS 50000
#define NJ 49999
#define B 1024
#define JC 38                // j-chunks (grid.x)
#define CHUNK 1344           // cols per chunk (21 tiles of 64)
#define NJ_PAD (JC*CHUNK)    // 51072
#define TILES 21
#define NCTA 304             // 38*8
#define LOG2E 1.4426950408889634f
#define KL_EPS 1e-7f
#define LG2_EPS -23.253496664211536f

// smem: two E buffers only
#define ES_STRIDE 144
#define ES_BYTES  (64*ES_STRIDE)      // 9216
#define SMEM_G6 (2*ES_BYTES)          // 18432

// ---------------- device scratch ----------------
__device__ __nv_bfloat16 g_eB[(size_t)NJ_PAD*64];
__device__ __nv_bfloat16 g_aBF[B*64];
__device__ float    g_acc[B*4];     // per-row {Z, T1, T2, T3}
__device__ unsigned g_minL[B];      // ordered-uint encoding of min logit
__device__ float    g_cross[B], g_lse2[B];
__device__ int      g_flag[B];
__device__ unsigned g_ctr;

// ---------------- helpers ----------------
__device__ __forceinline__ float ex2f_(float x){ float r; asm("ex2.approx.f32 %0, %1;" : "=f"(r) : "f"(x)); return r; }
__device__ __forceinline__ float lg2f_(float x){ float r; asm("lg2.approx.f32 %0, %1;" : "=f"(r) : "f"(x)); return r; }
__device__ __forceinline__ uint32_t smem_u32(const void* p){
    uint32_t a; asm("{ .reg .u64 t; cvta.to.shared.u64 t, %1; cvt.u32.u64 %0, t; }" : "=r"(a) : "l"(p)); return a; }
__device__ __forceinline__ unsigned ford(float f){           // monotone float->uint
    int i = __float_as_int(f);
    return (i >= 0) ? ((unsigned)i | 0x80000000u) : ~(unsigned)i;
}
__device__ __forceinline__ float forddec(unsigned u){
    int i = (u & 0x80000000u) ? (int)(u & 0x7FFFFFFFu) : ~(int)u;
    return __int_as_float(i);
}

__device__ __forceinline__ void mma16816(float* c, const uint32_t* a, uint32_t b0, uint32_t b1){
    asm volatile("mma.sync.aligned.m16n8k16.row.col.f32.bf16.bf16.f32 "
        "{%0,%1,%2,%3}, {%4,%5,%6,%7}, {%8,%9}, {%0,%1,%2,%3};"
        : "+f"(c[0]), "+f"(c[1]), "+f"(c[2]), "+f"(c[3])
        : "r"(a[0]), "r"(a[1]), "r"(a[2]), "r"(a[3]), "r"(b0), "r"(b1));
}

__device__ __forceinline__ void upd(float L, float y, float& z, float& t1, float& t2, float& t3, float& mn){
    y = fmaxf(y, KL_EPS);
    z += ex2f_(L);
    t1 = fmaf(y, L, t1);
    t2 += y;
    t3 = fmaf(y, lg2f_(y), t3);
    mn = fminf(mn, L);
}

// ---------------- kernel: normalize E[1:], bf16 [j][k], zero-pad ----------------
__global__ void k_enorm(const float* __restrict__ emb){
    int wid = threadIdx.x>>5, lane = threadIdx.x&31;
    int j = blockIdx.x*8 + wid;
    float2 v = make_float2(0.f, 0.f);
    if (j < NJ) v = ((const float2*)emb)[(size_t)(j+1)*32 + lane];
    float s = v.x*v.x + v.y*v.y;
#pragma unroll
    for(int o=16;o;o>>=1) s += __shfl_xor_sync(0xffffffffu, s, o);
    float inv = rsqrtf(fmaxf(s, 1e-12f));
    __nv_bfloat162 o2;
    o2.x = __float2bfloat16_rn(v.x*inv);
    o2.y = __float2bfloat16_rn(v.y*inv);
    ((__nv_bfloat162*)g_eB)[(size_t)j*32 + lane] = o2;
}

// ---------------- kernel: gather + MLP + l2norm, fold t*log2e, bf16 ----------------
__global__ void __launch_bounds__(256) k_mlp(const int* __restrict__ cards, const float* __restrict__ emb,
        const float* __restrict__ W1, const float* __restrict__ b1,
        const float* __restrict__ W2, const float* __restrict__ b2,
        const float* __restrict__ temp){
    extern __shared__ float dyn[];
    float* sW1 = dyn;              // 16384
    float* sW2 = dyn + 16384;      // 16384
    float* se  = dyn + 32768;      // 1024
    float* sh  = dyn + 33792;      // 4096
    float* so  = dyn + 37888;      // 1024
    float* ssc = dyn + 38912;      // 16
    int t = threadIdx.x;
    int b0 = blockIdx.x*16;
    const float4* W1v = (const float4*)W1; float4* s1v = (float4*)sW1;
    const float4* W2v = (const float4*)W2; float4* s2v = (float4*)sW2;
#pragma unroll
    for(int i=0;i<16;i++) s1v[t + i*256] = W1v[t + i*256];
#pragma unroll
    for(int i=0;i<16;i++) s2v[t + i*256] = W2v[t + i*256];
#pragma unroll
    for(int i=0;i<4;i++){ int idx = t + i*256; int bi = idx>>6, k = idx&63;
        se[idx] = emb[(size_t)cards[b0+bi]*64 + k]; }
    __syncthreads();
    float bb1 = b1[t];
    for(int bi=0;bi<16;bi++){
        float h = bb1;
#pragma unroll
        for(int k=0;k<64;k++) h = fmaf(se[bi*64+k], sW1[k*256+t], h);
        sh[bi*256+t] = fmaxf(h, 0.f);
    }
    __syncthreads();
    int d = t&63, g = t>>6;
    float bb2 = b2[d];
    for(int r=0;r<4;r++){
        int bi = g*4 + r;
        float o = bb2;
#pragma unroll 8
        for(int j=0;j<256;j++) o = fmaf(sh[bi*256+j], sW2[j*64+d], o);
        so[bi*64+d] = o;
    }
    __syncthreads();
    if (t < 16){
        float s = 0.f;
#pragma unroll
        for(int dd=0;dd<64;dd++){ float v = so[t*64+dd]; s = fmaf(v, v, s); }
        ssc[t] = temp[0]*LOG2E*rsqrtf(fmaxf(s, 1e-12f));
    }
    __syncthreads();
#pragma unroll
    for(int i=0;i<4;i++){ int idx = t + i*256; int bi = idx>>6;
        g_aBF[(size_t)b0*64 + idx] = __float2bfloat16_rn(so[idx]*ssc[bi]); }
}

// ---------------- kernel: init accumulators/counter/flags ----------------
__global__ void k_init(){
    int i = blockIdx.x*256 + threadIdx.x;   // grid 16 x 256 = 4096
    g_acc[i] = 0.f;
    if (i < B){ g_flag[i] = 0; g_minL[i] = 0xFFFFFFFFu; }
    if (i == 0) g_ctr = 0u;
}

// ---------------- E staging (16B cp.async, 2 per thread) ----------------
__device__ __forceinline__ void stage_E(int buf, int j0, uint32_t smbase, int tid){
    uint32_t eb = smbase + buf*ES_BYTES;
#pragma unroll
    for(int i=0;i<2;i++){
        int c = tid + i*256;
        int row = c>>3, seg = c&7;
        uint32_t dst = eb + row*ES_STRIDE + seg*16;
        const char* src = (const char*)g_eB + (size_t)(j0+row)*128 + seg*16;
        asm volatile("cp.async.cg.shared.global [%0], [%1], 16;" :: "r"(dst), "l"(src));
    }
    asm volatile("cp.async.commit_group;" ::: "memory");
}

// ---------------- kernel: HMMA GEMM + fused stats + last-CTA finalize ----------------
// grid (38, 8), 256 threads. M-tile 128, N-tile 64. adj read directly (fragment layout).
__global__ void __launch_bounds__(256) k_gemm6(const float* __restrict__ adj,
                                               const float* __restrict__ temp,
                                               float* __restrict__ out){
    extern __shared__ __align__(16) char sm6[];
    const uint32_t smbase = smem_u32(sm6);
    int tid = threadIdx.x;
    int wid = tid>>5, lane = tid&31, g = lane>>2, tg = lane&3;
    int jc = blockIdx.x, rt = blockIdx.y;
    int jstart = jc*CHUNK;
    int nvalid = NJ - jstart;
    int ntiles = (nvalid + 63)>>6; if (ntiles > TILES) ntiles = TILES;

    // A fragments: rows rt*128 + wid*16 + g (+8), all 4 k-tiles
    uint32_t A[4][4];
    int r0 = rt*128 + wid*16 + g;
    {
        const uint32_t* a0 = (const uint32_t*)(g_aBF + (size_t)r0*64);
        const uint32_t* a1 = (const uint32_t*)(g_aBF + (size_t)(r0+8)*64);
#pragma unroll
        for(int kt=0;kt<4;kt++){
            A[kt][0]=a0[kt*8+tg];   A[kt][1]=a1[kt*8+tg];
            A[kt][2]=a0[kt*8+tg+4]; A[kt][3]=a1[kt*8+tg+4];
        }
    }
    const float* arow0 = adj + (size_t)r0*NJ     + jstart + tg*2;
    const float* arow1 = adj + (size_t)(r0+8)*NJ + jstart + tg*2;

    float Z[2]={0.f,0.f}, T1[2]={0.f,0.f}, T2[2]={0.f,0.f}, T3[2]={0.f,0.f}, MN[2]={1e30f,1e30f};

    stage_E(0, jstart, smbase, tid);

    for(int t=0;t<ntiles;t++){
        int j0 = jstart + (t<<6);
        int jv = NJ - j0; if (jv > 64) jv = 64;
        bool hasNext = (t+1) < ntiles;
        if (hasNext){
            stage_E((t+1)&1, j0 + 64, smbase, tid);
            asm volatile("cp.async.wait_group 1;" ::: "memory");
        } else {
            asm volatile("cp.async.wait_group 0;" ::: "memory");
        }
        __syncthreads();

        const char* Es = sm6 + (t&1)*ES_BYTES;

        float acc[8][4];
#pragma unroll
        for(int nt=0;nt<8;nt++){ acc[nt][0]=0.f; acc[nt][1]=0.f; acc[nt][2]=0.f; acc[nt][3]=0.f; }

#pragma unroll
        for(int kt=0;kt<4;kt++){
#pragma unroll
            for(int nt=0;nt<8;nt++){
                const char* bp = Es + (nt*8+g)*ES_STRIDE + kt*32 + tg*4;
                uint32_t b0 = *(const uint32_t*)bp;
                uint32_t b1 = *(const uint32_t*)(bp + 16);
                mma16816(acc[nt], A[kt], b0, b1);
            }
        }

        int toff = t<<6;
        if (jv == 64){
#pragma unroll
            for(int nt=0;nt<8;nt++){
                int c0 = toff + nt*8;
                float ya0 = __ldcs(arow0 + c0),     ya1 = __ldcs(arow0 + c0 + 1);
                float yb0 = __ldcs(arow1 + c0),     yb1 = __ldcs(arow1 + c0 + 1);
                upd(acc[nt][0], ya0, Z[0],T1[0],T2[0],T3[0],MN[0]);
                upd(acc[nt][1], ya1, Z[0],T1[0],T2[0],T3[0],MN[0]);
                upd(acc[nt][2], yb0, Z[1],T1[1],T2[1],T3[1],MN[1]);
                upd(acc[nt][3], yb1, Z[1],T1[1],T2[1],T3[1],MN[1]);
            }
        } else {
#pragma unroll
            for(int nt=0;nt<8;nt++){
                int cl = nt*8 + tg*2;     // col within tile
                if (cl < jv){
                    int c0 = toff + nt*8;
                    float ya0 = __ldcs(arow0 + c0), yb0 = __ldcs(arow1 + c0);
                    upd(acc[nt][0], ya0, Z[0],T1[0],T2[0],T3[0],MN[0]);
                    upd(acc[nt][2], yb0, Z[1],T1[1],T2[1],T3[1],MN[1]);
                    if (cl + 1 < jv){
                        float ya1 = __ldcs(arow0 + c0 + 1), yb1 = __ldcs(arow1 + c0 + 1);
                        upd(acc[nt][1], ya1, Z[0],T1[0],T2[0],T3[0],MN[0]);
                        upd(acc[nt][3], yb1, Z[1],T1[1],T2[1],T3[1],MN[1]);
                    }
                }
            }
        }
        __syncthreads();   // protect E buffer reuse
    }

    // reduce over tg lanes, then atomic merge
#pragma unroll
    for(int r=0;r<2;r++){
#pragma unroll
        for(int off=1; off<4; off<<=1){
            Z[r]  += __shfl_xor_sync(0xffffffffu, Z[r],  off);
            T1[r] += __shfl_xor_sync(0xffffffffu, T1[r], off);
            T2[r] += __shfl_xor_sync(0xffffffffu, T2[r], off);
            T3[r] += __shfl_xor_sync(0xffffffffu, T3[r], off);
            MN[r]  = fminf(MN[r], __shfl_xor_sync(0xffffffffu, MN[r], off));
        }
    }
    if (tg == 0){
#pragma unroll
        for(int r=0;r<2;r++){
            int row = r0 + r*8;
            atomicAdd(&g_acc[row*4+0], Z[r]);
            atomicAdd(&g_acc[row*4+1], T1[r]);
            atomicAdd(&g_acc[row*4+2], T2[r]);
            atomicAdd(&g_acc[row*4+3], T3[r]);
            atomicMin(&g_minL[row], ford(MN[r]));
        }
    }

    // last CTA finalizes
    __threadfence();
    __shared__ unsigned s_last;
    if (tid == 0) s_last = (atomicAdd(&g_ctr, 1u) == NCTA-1) ? 1u : 0u;
    __syncthreads();
    if (!s_last) return;

    float* red = (float*)sm6;
    float T = temp[0];
    float local = 0.f;
#pragma unroll
    for(int i=0;i<4;i++){
        int b = tid + i*256;
        float Zb, T1b, T2b, T3b;
        asm("ld.global.cg.f32 %0, [%1];" : "=f"(Zb)  : "l"(&g_acc[b*4+0]));
        asm("ld.global.cg.f32 %0, [%1];" : "=f"(T1b) : "l"(&g_acc[b*4+1]));
        asm("ld.global.cg.f32 %0, [%1];" : "=f"(T2b) : "l"(&g_acc[b*4+2]));
        asm("ld.global.cg.f32 %0, [%1];" : "=f"(T3b) : "l"(&g_acc[b*4+3]));
        unsigned mu;
        asm("ld.global.cg.u32 %0, [%1];" : "=r"(mu) : "l"(&g_minL[b]));
        float lse2 = lg2f_(Zb);
        float cross = T1b - lse2*T2b;
        g_lse2[b] = lse2;
        g_cross[b] = cross;
        if (forddec(mu) - lse2 < LG2_EPS + 0.02f) g_flag[b] = 1;  // exact min, tiny margin
        local += T3b - cross;
    }
    red[tid] = local;
    __syncthreads();
    for(int s=128;s;s>>=1){ if (tid < s) red[tid] += red[tid+s]; __syncthreads(); }
    if (tid == 0) out[0] = red[0]*(1.0f/(float)B) + T*T*0.01f;
}

// ---------------- kernel: exact clipped fixup (cold, normally no-op) ----------------
__global__ void k_fixup(const float* __restrict__ adj, float* __restrict__ out){
    __shared__ int flags[128];
    __shared__ int any;
    __shared__ float a[64];
    __shared__ float red[256];
    int b0 = blockIdx.x*128;
    int t = threadIdx.x;
    if (t == 0) any = 0;
    __syncthreads();
    if (t < 128){ int f = g_flag[b0+t]; flags[t] = f; if (f) any = 1; }
    __syncthreads();
    if (!any) return;
    for(int r=0;r<128;r++){
        if (!flags[r]) continue;
        int b = b0 + r;
        if (t < 64) a[t] = __bfloat162float(g_aBF[b*64 + t]);
        __syncthreads();
        float lse2 = g_lse2[b];
        float cr = 0.f;
        for(int j=t; j<NJ; j+=256){
            float L = 0.f;
#pragma unroll
            for(int k=0;k<64;k++) L = fmaf(a[k], __bfloat162float(g_eB[(size_t)j*64 + k]), L);
            float y = fmaxf(adj[(size_t)b*NJ + j], KL_EPS);
            cr = fmaf(y, fmaxf(L - lse2, LG2_EPS), cr);
        }
        red[t] = cr; __syncthreads();
        for(int s=128;s;s>>=1){ if (t < s) red[t] += red[t+s]; __syncthreads(); }
        if (t == 0) atomicAdd(out, (g_cross[b] - red[0])*(1.0f/(float)B));
        __syncthreads();
    }
}

// ---------------- launch ----------------
extern "C" void kernel_launch(void* const* d_in, const int* in_sizes, int n_in,
                              void* d_out, int out_size){
    const int*   cards = (const int*)  d_in[0];
    const float* adj   = (const float*)d_in[1];
    const float* emb   = (const float*)d_in[2];
    const float* W1    = (const float*)d_in[3];
    const float* b1    = (const float*)d_in[4];
    const float* W2    = (const float*)d_in[5];
    const float* b2    = (const float*)d_in[6];
    const float* temp  = (const float*)d_in[7];

    cudaFuncSetAttribute(k_mlp,   cudaFuncAttributeMaxDynamicSharedMemorySize, 155712);
    cudaFuncSetAttribute(k_gemm6, cudaFuncAttributeMaxDynamicSharedMemorySize, SMEM_G6);

    k_enorm<<<NJ_PAD/8, 256>>>(emb);                               // idx 0
    k_mlp<<<64, 256, 155712>>>(cards, emb, W1, b1, W2, b2, temp);  // idx 1
    k_init<<<16, 256>>>();                                         // idx 2
    k_gemm6<<<dim3(JC, 8), 256, SMEM_G6>>>(adj, temp, (float*)d_out); // idx 3 (ncu target)
    k_fixup<<<8, 256>>>(adj, (float*)d_out);                       // idx 4
}

// round 9
// speedup vs baseline: 2208.9507x; 1.1862x over previous
#include <cuda_runtime.h>
#include <cuda_bf16.h>
#include <cstdint>

#define NCARDS 50000
#define NJ 49999
#define B 1024
#define NTOT 51198976ull     // B*NJ
#define JC 38
#define CHUNK 1344
#define NJ_PAD (JC*CHUNK)    // 51072
#define TILES 21
#define NCTA 304
#define LOG2E 1.4426950408889634f
#define KL_EPS 1e-7f
#define LG2_EPS -23.253496664211536f

// smem layout (bytes): E0[9216] E1[9216] ADJ0[34816] ADJ1[34816] = 88064
#define ES_STRIDE 144
#define ES_BYTES  9216
#define ADJ_STRIDE 68                 // floats per staged adj row (64 + alignment slack)
#define ADJ_BYTES (128*ADJ_STRIDE*4)  // 34816
#define ADJ_OFF   (2*ES_BYTES)        // 18432
#define SMEM_G7   (ADJ_OFF + 2*ADJ_BYTES)  // 88064

// ---------------- device scratch ----------------
__device__ __nv_bfloat16 g_eB[(size_t)NJ_PAD*64];
__device__ __nv_bfloat16 g_aBF[B*64];
__device__ float    g_acc[B*4];     // per-row {Z, T1, T2, T3}
__device__ unsigned g_minL[B];
__device__ unsigned g_ctr;

// ---------------- helpers ----------------
__device__ __forceinline__ float ex2f_(float x){ float r; asm("ex2.approx.f32 %0, %1;" : "=f"(r) : "f"(x)); return r; }
__device__ __forceinline__ float lg2f_(float x){ float r; asm("lg2.approx.f32 %0, %1;" : "=f"(r) : "f"(x)); return r; }
__device__ __forceinline__ uint32_t smem_u32(const void* p){
    uint32_t a; asm("{ .reg .u64 t; cvta.to.shared.u64 t, %1; cvt.u32.u64 %0, t; }" : "=r"(a) : "l"(p)); return a; }
__device__ __forceinline__ unsigned ford(float f){
    int i = __float_as_int(f);
    return (i >= 0) ? ((unsigned)i | 0x80000000u) : ~(unsigned)i;
}
__device__ __forceinline__ float forddec(unsigned u){
    int i = (u & 0x80000000u) ? (int)(u & 0x7FFFFFFFu) : ~(int)u;
    return __int_as_float(i);
}
__device__ __forceinline__ void mma16816(float* c, const uint32_t* a, uint32_t b0, uint32_t b1){
    asm volatile("mma.sync.aligned.m16n8k16.row.col.f32.bf16.bf16.f32 "
        "{%0,%1,%2,%3}, {%4,%5,%6,%7}, {%8,%9}, {%0,%1,%2,%3};"
        : "+f"(c[0]), "+f"(c[1]), "+f"(c[2]), "+f"(c[3])
        : "r"(a[0]), "r"(a[1]), "r"(a[2]), "r"(a[3]), "r"(b0), "r"(b1));
}
#define LDM4(r0,r1,r2,r3,addr) \
    asm volatile("ldmatrix.sync.aligned.m8n8.x4.shared.b16 {%0,%1,%2,%3}, [%4];" \
        : "=r"(r0), "=r"(r1), "=r"(r2), "=r"(r3) : "r"(addr))

__device__ __forceinline__ void upd(float L, float y, float& z, float& t1, float& t2, float& t3, float& mn){
    y = fmaxf(y, KL_EPS);
    z += ex2f_(L);
    t1 = fmaf(y, L, t1);
    t2 += y;
    t3 = fmaf(y, lg2f_(y), t3);
    mn = fminf(mn, L);
}

// ---------------- kernel: fused (normalize E[1:] -> bf16 [j][k], zero-pad) + init ----------------
__global__ void k_prep(const float* __restrict__ emb){
    if (blockIdx.x < NJ_PAD/8){
        int wid = threadIdx.x>>5, lane = threadIdx.x&31;
        int j = blockIdx.x*8 + wid;
        float2 v = make_float2(0.f, 0.f);
        if (j < NJ) v = ((const float2*)emb)[(size_t)(j+1)*32 + lane];
        float s = v.x*v.x + v.y*v.y;
#pragma unroll
        for(int o=16;o;o>>=1) s += __shfl_xor_sync(0xffffffffu, s, o);
        float inv = rsqrtf(fmaxf(s, 1e-12f));
        __nv_bfloat162 o2;
        o2.x = __float2bfloat16_rn(v.x*inv);
        o2.y = __float2bfloat16_rn(v.y*inv);
        ((__nv_bfloat162*)g_eB)[(size_t)j*32 + lane] = o2;
    } else {
        int i = (blockIdx.x - NJ_PAD/8)*256 + threadIdx.x;   // 16 blocks -> 4096
        g_acc[i] = 0.f;
        if (i < B) g_minL[i] = 0xFFFFFFFFu;
        if (i == 0) g_ctr = 0u;
    }
}

// ---------------- kernel: gather + MLP + l2norm, fold t*log2e, bf16 ----------------
__global__ void __launch_bounds__(256) k_mlp(const int* __restrict__ cards, const float* __restrict__ emb,
        const float* __restrict__ W1, const float* __restrict__ b1,
        const float* __restrict__ W2, const float* __restrict__ b2,
        const float* __restrict__ temp){
    extern __shared__ float dyn[];
    float* sW1 = dyn;              // 16384
    float* sW2 = dyn + 16384;      // 16384
    float* se  = dyn + 32768;      // 1024
    float* sh  = dyn + 33792;      // 4096
    float* so  = dyn + 37888;      // 1024
    float* ssc = dyn + 38912;      // 16
    int t = threadIdx.x;
    int b0 = blockIdx.x*16;
    const float4* W1v = (const float4*)W1; float4* s1v = (float4*)sW1;
    const float4* W2v = (const float4*)W2; float4* s2v = (float4*)sW2;
#pragma unroll
    for(int i=0;i<16;i++) s1v[t + i*256] = W1v[t + i*256];
#pragma unroll
    for(int i=0;i<16;i++) s2v[t + i*256] = W2v[t + i*256];
#pragma unroll
    for(int i=0;i<4;i++){ int idx = t + i*256; int bi = idx>>6, k = idx&63;
        se[idx] = emb[(size_t)cards[b0+bi]*64 + k]; }
    __syncthreads();
    float bb1 = b1[t];
    for(int bi=0;bi<16;bi++){
        float h = bb1;
#pragma unroll
        for(int k=0;k<64;k++) h = fmaf(se[bi*64+k], sW1[k*256+t], h);
        sh[bi*256+t] = fmaxf(h, 0.f);
    }
    __syncthreads();
    int d = t&63, g = t>>6;
    float bb2 = b2[d];
    for(int r=0;r<4;r++){
        int bi = g*4 + r;
        float o = bb2;
#pragma unroll 8
        for(int j=0;j<256;j++) o = fmaf(sh[bi*256+j], sW2[j*64+d], o);
        so[bi*64+d] = o;
    }
    __syncthreads();
    if (t < 16){
        float s = 0.f;
#pragma unroll
        for(int dd=0;dd<64;dd++){ float v = so[t*64+dd]; s = fmaf(v, v, s); }
        ssc[t] = temp[0]*LOG2E*rsqrtf(fmaxf(s, 1e-12f));
    }
    __syncthreads();
#pragma unroll
    for(int i=0;i<4;i++){ int idx = t + i*256; int bi = idx>>6;
        g_aBF[(size_t)b0*64 + idx] = __float2bfloat16_rn(so[idx]*ssc[bi]); }
}

// ---------------- staging: E (16B) + adj (16B alignment-corrected), one commit group ----------------
__device__ __forceinline__ void stage_tile(int buf, int j0, int rt, uint32_t smbase,
                                           const float* __restrict__ adj, int tid){
    uint32_t eb = smbase + buf*ES_BYTES;
#pragma unroll
    for(int i=0;i<2;i++){
        int c = tid + i*256;
        int row = c>>3, seg = c&7;
        uint32_t dst = eb + row*ES_STRIDE + seg*16;
        const char* src = (const char*)g_eB + (size_t)(j0+row)*128 + seg*16;
        asm volatile("cp.async.cg.shared.global [%0], [%1], 16;" :: "r"(dst), "l"(src));
    }
    uint32_t ab = smbase + ADJ_OFF + buf*ADJ_BYTES;
#pragma unroll
    for(int i=0;i<9;i++){
        unsigned idx = (unsigned)tid + i*256u;
        if (idx < 2176u){
            unsigned row = idx/17u, ch = idx - row*17u;
            size_t base = (size_t)(rt*128 + (int)row)*NJ + (unsigned)j0;
            size_t s = (base & ~(size_t)3) + ch*4u;
            uint32_t dst = ab + (row*ADJ_STRIDE + ch*4u)*4u;
            const float* src = adj + s;
            if (s + 4 <= NTOT){
                asm volatile("cp.async.cg.shared.global [%0], [%1], 16;" :: "r"(dst), "l"(src));
            } else {
#pragma unroll
                for(int e=0;e<4;e++){
                    float v = (s + e < NTOT) ? __ldcs(src + e) : 0.f;
                    asm volatile("st.shared.f32 [%0], %1;" :: "r"(dst + e*4u), "f"(v));
                }
            }
        }
    }
    asm volatile("cp.async.commit_group;" ::: "memory");
}

// ---------------- kernel: HMMA GEMM + fused stats + last-CTA finalize (incl. inline fixup) ----------------
// grid (38, 8), 256 threads. M-tile 128, N-tile 64.
__global__ void __launch_bounds__(256) k_gemm7(const float* __restrict__ adj,
                                               const float* __restrict__ temp,
                                               float* __restrict__ out){
    extern __shared__ __align__(16) char sm7[];
    const uint32_t smbase = smem_u32(sm7);
    int tid = threadIdx.x;
    int wid = tid>>5, lane = tid&31, g = lane>>2, tg = lane&3;
    int jc = blockIdx.x, rt = blockIdx.y;
    int jstart = jc*CHUNK;
    int nvalid = NJ - jstart;
    int ntiles = (nvalid + 63)>>6; if (ntiles > TILES) ntiles = TILES;

    int r0l = wid*16 + g;
    int r0g = rt*128 + r0l;

    // A fragments
    uint32_t A[4][4];
    {
        const uint32_t* a0 = (const uint32_t*)(g_aBF + (size_t)r0g*64);
        const uint32_t* a1 = (const uint32_t*)(g_aBF + (size_t)(r0g+8)*64);
#pragma unroll
        for(int kt=0;kt<4;kt++){
            A[kt][0]=a0[kt*8+tg];   A[kt][1]=a1[kt*8+tg];
            A[kt][2]=a0[kt*8+tg+4]; A[kt][3]=a1[kt*8+tg+4];
        }
    }
    // alignment shift: constant across tiles (64 ≡ 0 mod 4) and equal for rows r0g, r0g+8
    const int ash = (int)(((size_t)r0g*NJ + (unsigned)jstart) & 3);
    // ldmatrix per-lane offset within E buffer
    const uint32_t lmo = (uint32_t)((lane&7)*ES_STRIDE + (lane>>3)*16);

    float Z[2]={0.f,0.f}, T1[2]={0.f,0.f}, T2[2]={0.f,0.f}, T3[2]={0.f,0.f}, MN[2]={1e30f,1e30f};

    stage_tile(0, jstart, rt, smbase, adj, tid);

    for(int t=0;t<ntiles;t++){
        int j0 = jstart + (t<<6);
        int jv = NJ - j0; if (jv > 64) jv = 64;
        bool hasNext = (t+1) < ntiles;
        if (hasNext){
            stage_tile((t+1)&1, j0 + 64, rt, smbase, adj, tid);
            asm volatile("cp.async.wait_group 1;" ::: "memory");
        } else {
            asm volatile("cp.async.wait_group 0;" ::: "memory");
        }
        __syncthreads();

        uint32_t esb = smbase + (t&1)*ES_BYTES + lmo;
        const float* sa = (const float*)(sm7 + ADJ_OFF + (t&1)*ADJ_BYTES);
        const float* srow0 = sa + r0l*ADJ_STRIDE + ash;
        const float* srow1 = srow0 + 8*ADJ_STRIDE;

        float acc[8][4];
#pragma unroll
        for(int nt=0;nt<8;nt++){ acc[nt][0]=0.f; acc[nt][1]=0.f; acc[nt][2]=0.f; acc[nt][3]=0.f; }

#pragma unroll
        for(int nt=0;nt<8;nt++){
            uint32_t ad = esb + nt*(8*ES_STRIDE);
            uint32_t b00,b01,b10,b11, b20,b21,b30,b31;
            LDM4(b00,b01,b10,b11, ad);
            LDM4(b20,b21,b30,b31, ad + 64);
            mma16816(acc[nt], A[0], b00, b01);
            mma16816(acc[nt], A[1], b10, b11);
            mma16816(acc[nt], A[2], b20, b21);
            mma16816(acc[nt], A[3], b30, b31);
        }

        if (jv == 64){
#pragma unroll
            for(int nt=0;nt<8;nt++){
                int c = nt*8 + tg*2;
                float ya0 = srow0[c], ya1 = srow0[c+1];
                float yb0 = srow1[c], yb1 = srow1[c+1];
                upd(acc[nt][0], ya0, Z[0],T1[0],T2[0],T3[0],MN[0]);
                upd(acc[nt][1], ya1, Z[0],T1[0],T2[0],T3[0],MN[0]);
                upd(acc[nt][2], yb0, Z[1],T1[1],T2[1],T3[1],MN[1]);
                upd(acc[nt][3], yb1, Z[1],T1[1],T2[1],T3[1],MN[1]);
            }
        } else {
#pragma unroll
            for(int nt=0;nt<8;nt++){
                int c = nt*8 + tg*2;
                if (c < jv){
                    upd(acc[nt][0], srow0[c], Z[0],T1[0],T2[0],T3[0],MN[0]);
                    upd(acc[nt][2], srow1[c], Z[1],T1[1],T2[1],T3[1],MN[1]);
                    if (c + 1 < jv){
                        upd(acc[nt][1], srow0[c+1], Z[0],T1[0],T2[0],T3[0],MN[0]);
                        upd(acc[nt][3], srow1[c+1], Z[1],T1[1],T2[1],T3[1],MN[1]);
                    }
                }
            }
        }
        __syncthreads();
    }

    // reduce over tg lanes, atomic merge
#pragma unroll
    for(int r=0;r<2;r++){
#pragma unroll
        for(int off=1; off<4; off<<=1){
            Z[r]  += __shfl_xor_sync(0xffffffffu, Z[r],  off);
            T1[r] += __shfl_xor_sync(0xffffffffu, T1[r], off);
            T2[r] += __shfl_xor_sync(0xffffffffu, T2[r], off);
            T3[r] += __shfl_xor_sync(0xffffffffu, T3[r], off);
            MN[r]  = fminf(MN[r], __shfl_xor_sync(0xffffffffu, MN[r], off));
        }
    }
    if (tg == 0){
#pragma unroll
        for(int r=0;r<2;r++){
            int row = r0g + r*8;
            atomicAdd(&g_acc[row*4+0], Z[r]);
            atomicAdd(&g_acc[row*4+1], T1[r]);
            atomicAdd(&g_acc[row*4+2], T2[r]);
            atomicAdd(&g_acc[row*4+3], T3[r]);
            atomicMin(&g_minL[row], ford(MN[r]));
        }
    }

    // ---- last CTA finalizes (incl. inline exact-clip fixup, expected no-op) ----
    __threadfence();
    __shared__ unsigned s_last;
    if (tid == 0) s_last = (atomicAdd(&g_ctr, 1u) == NCTA-1) ? 1u : 0u;
    __syncthreads();
    if (!s_last) return;

    float* t3s = (float*)(sm7 + ADJ_OFF);   // [1024]
    float* crs = t3s + 1024;                // [1024]
    float* ls2 = crs + 1024;                // [1024]
    float* red = ls2 + 1024;                // [256]
    float* aa  = red + 256;                 // [64]
    __shared__ unsigned fl[32];
    __shared__ int s_any;
    if (tid < 32) fl[tid] = 0u;
    if (tid == 0) s_any = 0;
    __syncthreads();

    float T = temp[0];
#pragma unroll
    for(int i=0;i<4;i++){
        int b = tid + i*256;
        float Zb, T1b, T2b, T3b; unsigned mu;
        asm("ld.global.cg.f32 %0, [%1];" : "=f"(Zb)  : "l"(&g_acc[b*4+0]));
        asm("ld.global.cg.f32 %0, [%1];" : "=f"(T1b) : "l"(&g_acc[b*4+1]));
        asm("ld.global.cg.f32 %0, [%1];" : "=f"(T2b) : "l"(&g_acc[b*4+2]));
        asm("ld.global.cg.f32 %0, [%1];" : "=f"(T3b) : "l"(&g_acc[b*4+3]));
        asm("ld.global.cg.u32 %0, [%1];" : "=r"(mu)  : "l"(&g_minL[b]));
        float lse2 = lg2f_(Zb);
        float cross = T1b - lse2*T2b;
        t3s[b] = T3b; crs[b] = cross; ls2[b] = lse2;
        if (forddec(mu) - lse2 < LG2_EPS + 0.02f){
            atomicOr(&fl[b>>5], 1u<<(b&31));
            s_any = 1;
        }
    }
    __syncthreads();

    if (s_any){   // cold path: exact clipped recompute per flagged row
        for(int b=0;b<B;b++){
            if (!((fl[b>>5]>>(b&31)) & 1u)) continue;
            if (tid < 64) aa[tid] = __bfloat162float(g_aBF[b*64 + tid]);
            __syncthreads();
            float lse2 = ls2[b];
            float cr = 0.f;
            for(int j=tid; j<NJ; j+=256){
                float L = 0.f;
#pragma unroll
                for(int k=0;k<64;k++) L = fmaf(aa[k], __bfloat162float(g_eB[(size_t)j*64 + k]), L);
                float y = fmaxf(adj[(size_t)b*NJ + j], KL_EPS);
                cr = fmaf(y, fmaxf(L - lse2, LG2_EPS), cr);
            }
            red[tid] = cr; __syncthreads();
            for(int s=128;s;s>>=1){ if (tid < s) red[tid] += red[tid+s]; __syncthreads(); }
            if (tid == 0) crs[b] = red[0];
            __syncthreads();
        }
    }

    float local = 0.f;
#pragma unroll
    for(int i=0;i<4;i++){ int b = tid + i*256; local += t3s[b] - crs[b]; }
    red[tid] = local;
    __syncthreads();
    for(int s=128;s;s>>=1){ if (tid < s) red[tid] += red[tid+s]; __syncthreads(); }
    if (tid == 0) out[0] = red[0]*(1.0f/(float)B) + T*T*0.01f;
}

// ---------------- launch ----------------
extern "C" void kernel_launch(void* const* d_in, const int* in_sizes, int n_in,
                              void* d_out, int out_size){
    const int*   cards = (const int*)  d_in[0];
    const float* adj   = (const float*)d_in[1];
    const float* emb   = (const float*)d_in[2];
    const float* W1    = (const float*)d_in[3];
    const float* b1    = (const float*)d_in[4];
    const float* W2    = (const float*)d_in[5];
    const float* b2    = (const float*)d_in[6];
    const float* temp  = (const float*)d_in[7];

    cudaFuncSetAttribute(k_mlp,   cudaFuncAttributeMaxDynamicSharedMemorySize, 155712);
    cudaFuncSetAttribute(k_gemm7, cudaFuncAttributeMaxDynamicSharedMemorySize, SMEM_G7);

    k_prep<<<NJ_PAD/8 + 16, 256>>>(emb);                           // idx 0
    k_mlp<<<64, 256, 155712>>>(cards, emb, W1, b1, W2, b2, temp);  // idx 1
    k_gemm7<<<dim3(JC, 8), 256, SMEM_G7>>>(adj, temp, (float*)d_out); // idx 2
}

// round 10
// speedup vs baseline: 2250.4633x; 1.0188x over previous
#include <cuda_runtime.h>
#include <cuda_bf16.h>
#include <cstdint>

#define NCARDS 50000
#define NJ 49999
#define B 1024
#define NTOT 51198976ull     // B*NJ
#define JC 38
#define CHUNK 1344
#define NJ_PAD (JC*CHUNK)    // 51072
#define TILES 21
#define NCTA 608             // 38*16
#define LOG2E 1.4426950408889634f
#define KL_EPS 1e-7f
#define LG2_EPS -23.253496664211536f

// smem layout (bytes): E0[9216] E1[9216] ADJ0[17408] ADJ1[17408] = 53248
#define ES_STRIDE 144
#define ES_BYTES  9216                 // 64 rows * 144
#define ADJ_STRIDE 68                  // floats per staged adj row
#define ADJ_BYTES (64*ADJ_STRIDE*4)    // 17408
#define ADJ_OFF   (2*ES_BYTES)         // 18432
#define SMEM_G8   (ADJ_OFF + 2*ADJ_BYTES)  // 53248

// ---------------- device scratch ----------------
__device__ __nv_bfloat16 g_eB[(size_t)NJ_PAD*64];
__device__ __nv_bfloat16 g_aBF[B*64];
__device__ float    g_acc[B*4];
__device__ unsigned g_minL[B];
__device__ float    g_cross[B], g_lse2[B];
__device__ int      g_flag[B];
__device__ unsigned g_ctr;

// ---------------- helpers ----------------
__device__ __forceinline__ float ex2f_(float x){ float r; asm("ex2.approx.f32 %0, %1;" : "=f"(r) : "f"(x)); return r; }
__device__ __forceinline__ float lg2f_(float x){ float r; asm("lg2.approx.f32 %0, %1;" : "=f"(r) : "f"(x)); return r; }
__device__ __forceinline__ uint32_t smem_u32(const void* p){
    uint32_t a; asm("{ .reg .u64 t; cvta.to.shared.u64 t, %1; cvt.u32.u64 %0, t; }" : "=r"(a) : "l"(p)); return a; }
__device__ __forceinline__ unsigned ford(float f){
    int i = __float_as_int(f);
    return (i >= 0) ? ((unsigned)i | 0x80000000u) : ~(unsigned)i;
}
__device__ __forceinline__ float forddec(unsigned u){
    int i = (u & 0x80000000u) ? (int)(u & 0x7FFFFFFFu) : ~(int)u;
    return __int_as_float(i);
}
__device__ __forceinline__ void mma16816(float* c, const uint32_t* a, uint32_t b0, uint32_t b1){
    asm volatile("mma.sync.aligned.m16n8k16.row.col.f32.bf16.bf16.f32 "
        "{%0,%1,%2,%3}, {%4,%5,%6,%7}, {%8,%9}, {%0,%1,%2,%3};"
        : "+f"(c[0]), "+f"(c[1]), "+f"(c[2]), "+f"(c[3])
        : "r"(a[0]), "r"(a[1]), "r"(a[2]), "r"(a[3]), "r"(b0), "r"(b1));
}
#define LDM4(r0,r1,r2,r3,addr) \
    asm volatile("ldmatrix.sync.aligned.m8n8.x4.shared.b16 {%0,%1,%2,%3}, [%4];" \
        : "=r"(r0), "=r"(r1), "=r"(r2), "=r"(r3) : "r"(addr))

__device__ __forceinline__ void upd(float L, float y, float& z, float& t1, float& t2, float& t3, float& mn){
    y = fmaxf(y, KL_EPS);
    z += ex2f_(L);
    t1 = fmaf(y, L, t1);
    t2 += y;
    t3 = fmaf(y, lg2f_(y), t3);
    mn = fminf(mn, L);
}

// ---------------- kernel 0: normalize E[1:], 4 rows/warp for ILP ----------------
__global__ void k_enorm(const float* __restrict__ emb){
    int wid = threadIdx.x>>5, lane = threadIdx.x&31;
    int jb = (blockIdx.x*8 + wid)*4;
    float2 v[4]; float s[4];
#pragma unroll
    for(int r=0;r<4;r++){
        int j = jb + r;
        v[r] = make_float2(0.f, 0.f);
        if (j < NJ) v[r] = ((const float2*)emb)[(size_t)(j+1)*32 + lane];
        s[r] = v[r].x*v[r].x + v[r].y*v[r].y;
    }
#pragma unroll
    for(int o=16;o;o>>=1){
#pragma unroll
        for(int r=0;r<4;r++) s[r] += __shfl_xor_sync(0xffffffffu, s[r], o);
    }
#pragma unroll
    for(int r=0;r<4;r++){
        int j = jb + r;
        if (j < NJ_PAD){
            float inv = rsqrtf(fmaxf(s[r], 1e-12f));
            __nv_bfloat162 o2;
            o2.x = __float2bfloat16_rn(v[r].x*inv);
            o2.y = __float2bfloat16_rn(v[r].y*inv);
            ((__nv_bfloat162*)g_eB)[(size_t)j*32 + lane] = o2;
        }
    }
}

// ---------------- kernel 1: gather + MLP + l2norm, fold t*log2e (8 rows/block, 128 blocks) ----------------
__global__ void __launch_bounds__(256) k_mlp(const int* __restrict__ cards, const float* __restrict__ emb,
        const float* __restrict__ W1, const float* __restrict__ b1,
        const float* __restrict__ W2, const float* __restrict__ b2,
        const float* __restrict__ temp){
    extern __shared__ float dyn[];
    float* sW1 = dyn;              // 16384
    float* sW2 = dyn + 16384;      // 16384
    float* se  = dyn + 32768;      // 512
    float* sh  = dyn + 33280;      // 2048
    float* so  = dyn + 35328;      // 512
    float* ssc = dyn + 35840;      // 8
    int t = threadIdx.x;
    int b0 = blockIdx.x*8;
    const float4* W1v = (const float4*)W1; float4* s1v = (float4*)sW1;
    const float4* W2v = (const float4*)W2; float4* s2v = (float4*)sW2;
#pragma unroll
    for(int i=0;i<16;i++) s1v[t + i*256] = W1v[t + i*256];
#pragma unroll
    for(int i=0;i<16;i++) s2v[t + i*256] = W2v[t + i*256];
#pragma unroll
    for(int i=0;i<2;i++){ int idx = t + i*256; int bi = idx>>6, k = idx&63;
        se[idx] = emb[(size_t)cards[b0+bi]*64 + k]; }
    __syncthreads();
    float bb1 = b1[t];
#pragma unroll
    for(int bi=0;bi<8;bi++){
        float h = bb1;
#pragma unroll
        for(int k=0;k<64;k++) h = fmaf(se[bi*64+k], sW1[k*256+t], h);
        sh[bi*256+t] = fmaxf(h, 0.f);
    }
    __syncthreads();
    int d = t&63, q = t>>6;
    float bb2 = b2[d];
#pragma unroll
    for(int r=0;r<2;r++){
        int bi = q*2 + r;
        float o = bb2;
#pragma unroll 8
        for(int j=0;j<256;j++) o = fmaf(sh[bi*256+j], sW2[j*64+d], o);
        so[bi*64+d] = o;
    }
    __syncthreads();
    if (t < 8){
        float s = 0.f;
#pragma unroll
        for(int dd=0;dd<64;dd++){ float v = so[t*64+dd]; s = fmaf(v, v, s); }
        ssc[t] = temp[0]*LOG2E*rsqrtf(fmaxf(s, 1e-12f));
    }
    __syncthreads();
#pragma unroll
    for(int i=0;i<2;i++){ int idx = t + i*256; int bi = idx>>6;
        g_aBF[(size_t)b0*64 + idx] = __float2bfloat16_rn(so[idx]*ssc[bi]); }
}

// ---------------- kernel 2: init ----------------
__global__ void k_init(){
    int i = blockIdx.x*256 + threadIdx.x;   // 16x256 = 4096
    g_acc[i] = 0.f;
    if (i < B){ g_minL[i] = 0xFFFFFFFFu; g_flag[i] = 0; }
    if (i == 0) g_ctr = 0u;
}

// ---------------- staging: E (16B) + adj (16B aligned superset) ----------------
__device__ __forceinline__ void stage_tile(int buf, int j0, int rt, uint32_t smbase,
                                           const float* __restrict__ adj, int tid){
    uint32_t eb = smbase + buf*ES_BYTES;
#pragma unroll
    for(int i=0;i<2;i++){
        int c = tid + i*256;                  // 512 chunks: 64 rows x 8
        int row = c>>3, seg = c&7;
        uint32_t dst = eb + row*ES_STRIDE + seg*16;
        const char* src = (const char*)g_eB + (size_t)(j0+row)*128 + seg*16;
        asm volatile("cp.async.cg.shared.global [%0], [%1], 16;" :: "r"(dst), "l"(src));
    }
    uint32_t ab = smbase + ADJ_OFF + buf*ADJ_BYTES;
#pragma unroll
    for(int i=0;i<5;i++){
        unsigned idx = (unsigned)tid + i*256u;
        if (idx < 1088u){                     // 64 rows x 17 chunks
            unsigned row = idx/17u, ch = idx - row*17u;
            size_t base = (size_t)(rt*64 + (int)row)*NJ + (unsigned)j0;
            size_t s = (base & ~(size_t)3) + ch*4u;
            uint32_t dst = ab + (row*ADJ_STRIDE + ch*4u)*4u;
            const float* src = adj + s;
            if (s + 4 <= NTOT){
                asm volatile("cp.async.cg.shared.global [%0], [%1], 16;" :: "r"(dst), "l"(src));
            } else {
#pragma unroll
                for(int e=0;e<4;e++){
                    float v = (s + e < NTOT) ? __ldcs(src + e) : 0.f;
                    asm volatile("st.shared.f32 [%0], %1;" :: "r"(dst + e*4u), "f"(v));
                }
            }
        }
    }
    asm volatile("cp.async.commit_group;" ::: "memory");
}

// ---------------- kernel 3: HMMA GEMM + fused stats + last-CTA finalize ----------------
// grid (38, 16), 256 threads, 4 CTAs/SM. M-tile 64, N-tile 64. Warp grid 4m x 2n.
__global__ void __launch_bounds__(256, 4) k_gemm8(const float* __restrict__ adj,
                                                  const float* __restrict__ temp,
                                                  float* __restrict__ out){
    extern __shared__ __align__(16) char sm8[];
    const uint32_t smbase = smem_u32(sm8);
    int tid = threadIdx.x;
    int wid = tid>>5, lane = tid&31, g = lane>>2, tg = lane&3;
    int wr = wid&3, wc = wid>>2;             // warp row (0..3), warp col (0..1)
    int jc = blockIdx.x, rt = blockIdx.y;
    int jstart = jc*CHUNK;
    int nvalid = NJ - jstart;
    int ntiles = (nvalid + 63)>>6; if (ntiles > TILES) ntiles = TILES;

    int r0l = wr*16 + g;                     // local row (0..63)
    int r0g = rt*64 + r0l;                   // global row

    uint32_t A[4][4];
    {
        const uint32_t* a0 = (const uint32_t*)(g_aBF + (size_t)r0g*64);
        const uint32_t* a1 = (const uint32_t*)(g_aBF + (size_t)(r0g+8)*64);
#pragma unroll
        for(int kt=0;kt<4;kt++){
            A[kt][0]=a0[kt*8+tg];   A[kt][1]=a1[kt*8+tg];
            A[kt][2]=a0[kt*8+tg+4]; A[kt][3]=a1[kt*8+tg+4];
        }
    }
    const int ash = (int)(((size_t)r0g*NJ + (unsigned)jstart) & 3);   // same for r0g+8 (8*NJ%4==0)
    const uint32_t lmo = (uint32_t)((wc*32 + (lane&7))*ES_STRIDE + (lane>>3)*16);

    float Z[2]={0.f,0.f}, T1[2]={0.f,0.f}, T2[2]={0.f,0.f}, T3[2]={0.f,0.f}, MN[2]={1e30f,1e30f};

    stage_tile(0, jstart, rt, smbase, adj, tid);

    for(int t=0;t<ntiles;t++){
        int j0 = jstart + (t<<6);
        int jv = NJ - j0; if (jv > 64) jv = 64;
        bool hasNext = (t+1) < ntiles;
        if (hasNext){
            stage_tile((t+1)&1, j0 + 64, rt, smbase, adj, tid);
            asm volatile("cp.async.wait_group 1;" ::: "memory");
        } else {
            asm volatile("cp.async.wait_group 0;" ::: "memory");
        }
        __syncthreads();

        uint32_t esb = smbase + (t&1)*ES_BYTES + lmo;
        const float* sa = (const float*)(sm8 + ADJ_OFF + (t&1)*ADJ_BYTES);
        const float* srow0 = sa + r0l*ADJ_STRIDE + ash;
        const float* srow1 = srow0 + 8*ADJ_STRIDE;

        float acc[4][4];
#pragma unroll
        for(int nt=0;nt<4;nt++){ acc[nt][0]=0.f; acc[nt][1]=0.f; acc[nt][2]=0.f; acc[nt][3]=0.f; }

#pragma unroll
        for(int nt=0;nt<4;nt++){
            uint32_t ad = esb + nt*(8*ES_STRIDE);
            uint32_t b00,b01,b10,b11, b20,b21,b30,b31;
            LDM4(b00,b01,b10,b11, ad);
            LDM4(b20,b21,b30,b31, ad + 64);
            mma16816(acc[nt], A[0], b00, b01);
            mma16816(acc[nt], A[1], b10, b11);
            mma16816(acc[nt], A[2], b20, b21);
            mma16816(acc[nt], A[3], b30, b31);
        }

        if (jv == 64){
#pragma unroll
            for(int nt=0;nt<4;nt++){
                int c = wc*32 + nt*8 + tg*2;
                float ya0 = srow0[c], ya1 = srow0[c+1];
                float yb0 = srow1[c], yb1 = srow1[c+1];
                upd(acc[nt][0], ya0, Z[0],T1[0],T2[0],T3[0],MN[0]);
                upd(acc[nt][1], ya1, Z[0],T1[0],T2[0],T3[0],MN[0]);
                upd(acc[nt][2], yb0, Z[1],T1[1],T2[1],T3[1],MN[1]);
                upd(acc[nt][3], yb1, Z[1],T1[1],T2[1],T3[1],MN[1]);
            }
        } else {
#pragma unroll
            for(int nt=0;nt<4;nt++){
                int c = wc*32 + nt*8 + tg*2;
                if (c < jv){
                    upd(acc[nt][0], srow0[c], Z[0],T1[0],T2[0],T3[0],MN[0]);
                    upd(acc[nt][2], srow1[c], Z[1],T1[1],T2[1],T3[1],MN[1]);
                    if (c + 1 < jv){
                        upd(acc[nt][1], srow0[c+1], Z[0],T1[0],T2[0],T3[0],MN[0]);
                        upd(acc[nt][3], srow1[c+1], Z[1],T1[1],T2[1],T3[1],MN[1]);
                    }
                }
            }
        }
        __syncthreads();
    }

    // reduce over tg lanes, atomic merge (both warp-cols hit same rows; atomics handle it)
#pragma unroll
    for(int r=0;r<2;r++){
#pragma unroll
        for(int off=1; off<4; off<<=1){
            Z[r]  += __shfl_xor_sync(0xffffffffu, Z[r],  off);
            T1[r] += __shfl_xor_sync(0xffffffffu, T1[r], off);
            T2[r] += __shfl_xor_sync(0xffffffffu, T2[r], off);
            T3[r] += __shfl_xor_sync(0xffffffffu, T3[r], off);
            MN[r]  = fminf(MN[r], __shfl_xor_sync(0xffffffffu, MN[r], off));
        }
    }
    if (tg == 0){
#pragma unroll
        for(int r=0;r<2;r++){
            int row = r0g + r*8;
            atomicAdd(&g_acc[row*4+0], Z[r]);
            atomicAdd(&g_acc[row*4+1], T1[r]);
            atomicAdd(&g_acc[row*4+2], T2[r]);
            atomicAdd(&g_acc[row*4+3], T3[r]);
            atomicMin(&g_minL[row], ford(MN[r]));
        }
    }

    // ---- last CTA finalizes ----
    __threadfence();
    __shared__ unsigned s_last;
    if (tid == 0) s_last = (atomicAdd(&g_ctr, 1u) == NCTA-1) ? 1u : 0u;
    __syncthreads();
    if (!s_last) return;

    float* red = (float*)sm8;   // reuse smem
    float T = temp[0];
    float local = 0.f;
#pragma unroll
    for(int i=0;i<4;i++){
        int b = tid + i*256;
        float Zb, T1b, T2b, T3b; unsigned mu;
        asm("ld.global.cg.f32 %0, [%1];" : "=f"(Zb)  : "l"(&g_acc[b*4+0]));
        asm("ld.global.cg.f32 %0, [%1];" : "=f"(T1b) : "l"(&g_acc[b*4+1]));
        asm("ld.global.cg.f32 %0, [%1];" : "=f"(T2b) : "l"(&g_acc[b*4+2]));
        asm("ld.global.cg.f32 %0, [%1];" : "=f"(T3b) : "l"(&g_acc[b*4+3]));
        asm("ld.global.cg.u32 %0, [%1];" : "=r"(mu)  : "l"(&g_minL[b]));
        float lse2 = lg2f_(Zb);
        float cross = T1b - lse2*T2b;
        g_lse2[b] = lse2;
        g_cross[b] = cross;
        if (forddec(mu) - lse2 < LG2_EPS + 0.02f) g_flag[b] = 1;
        local += T3b - cross;
    }
    red[tid] = local;
    __syncthreads();
    for(int s=128;s;s>>=1){ if (tid < s) red[tid] += red[tid+s]; __syncthreads(); }
    if (tid == 0) out[0] = red[0]*(1.0f/(float)B) + T*T*0.01f;
}

// ---------------- kernel 4: exact clipped fixup (cold, normally no-op) ----------------
__global__ void k_fixup(const float* __restrict__ adj, float* __restrict__ out){
    __shared__ int flags[128];
    __shared__ int any;
    __shared__ float a[64];
    __shared__ float red[256];
    int b0 = blockIdx.x*128;
    int t = threadIdx.x;
    if (t == 0) any = 0;
    __syncthreads();
    if (t < 128){ int f = g_flag[b0+t]; flags[t] = f; if (f) any = 1; }
    __syncthreads();
    if (!any) return;
    for(int r=0;r<128;r++){
        if (!flags[r]) continue;
        int b = b0 + r;
        if (t < 64) a[t] = __bfloat162float(g_aBF[b*64 + t]);
        __syncthreads();
        float lse2 = g_lse2[b];
        float cr = 0.f;
        for(int j=t; j<NJ; j+=256){
            float L = 0.f;
#pragma unroll
            for(int k=0;k<64;k++) L = fmaf(a[k], __bfloat162float(g_eB[(size_t)j*64 + k]), L);
            float y = fmaxf(adj[(size_t)b*NJ + j], KL_EPS);
            cr = fmaf(y, fmaxf(L - lse2, LG2_EPS), cr);
        }
        red[t] = cr; __syncthreads();
        for(int s=128;s;s>>=1){ if (t < s) red[t] += red[t+s]; __syncthreads(); }
        if (t == 0) atomicAdd(out, (g_cross[b] - red[0])*(1.0f/(float)B));
        __syncthreads();
    }
}

// ---------------- launch ----------------
extern "C" void kernel_launch(void* const* d_in, const int* in_sizes, int n_in,
                              void* d_out, int out_size){
    const int*   cards = (const int*)  d_in[0];
    const float* adj   = (const float*)d_in[1];
    const float* emb   = (const float*)d_in[2];
    const float* W1    = (const float*)d_in[3];
    const float* b1    = (const float*)d_in[4];
    const float* W2    = (const float*)d_in[5];
    const float* b2    = (const float*)d_in[6];
    const float* temp  = (const float*)d_in[7];

    cudaFuncSetAttribute(k_mlp,   cudaFuncAttributeMaxDynamicSharedMemorySize, 143392);
    cudaFuncSetAttribute(k_gemm8, cudaFuncAttributeMaxDynamicSharedMemorySize, SMEM_G8);

    k_enorm<<<1596, 256>>>(emb);                                   // idx 0
    k_mlp<<<128, 256, 143392>>>(cards, emb, W1, b1, W2, b2, temp); // idx 1
    k_init<<<16, 256>>>();                                         // idx 2
    k_gemm8<<<dim3(JC, 16), 256, SMEM_G8>>>(adj, temp, (float*)d_out); // idx 3 (ncu target)
    k_fixup<<<8, 256>>>(adj, (float*)d_out);                       // idx 4
}